// round 17
// baseline (speedup 1.0000x reference)
#include <cuda_runtime.h>
#include <math.h>

// Problem constants
#define Bsz 2
#define Ssz 2048
#define Dsz 1024
#define Hsz 16
#define DKsz 64
#define BHsz (Bsz * Hsz)

// Scratch (allocation-free rule: __device__ globals)
__device__ float g_Q[(long)Bsz * Ssz * Dsz];
__device__ float g_K[(long)Bsz * Ssz * Dsz];
__device__ float g_V[(long)Bsz * Ssz * Dsz];
__device__ float g_X[(long)Bsz * Ssz * Dsz];
// Per-row exp-sums (full row sum, computed by fused kernel)
__device__ float g_S[(long)BHsz * Ssz];

__device__ __forceinline__ unsigned f2tf(float f) {
    unsigned u;
    asm("cvt.rna.tf32.f32 %0, %1;" : "=r"(u) : "f"(f));
    return u;
}

__device__ __forceinline__ void mma_tf32(float c[4], unsigned a0, unsigned a1,
                                         unsigned a2, unsigned a3,
                                         unsigned b0, unsigned b1) {
    asm volatile(
        "mma.sync.aligned.m16n8k8.row.col.f32.tf32.tf32.f32 "
        "{%0,%1,%2,%3}, {%4,%5,%6,%7}, {%8,%9}, {%0,%1,%2,%3};"
        : "+f"(c[0]), "+f"(c[1]), "+f"(c[2]), "+f"(c[3])
        : "r"(a0), "r"(a1), "r"(a2), "r"(a3), "r"(b0), "r"(b1));
}

// ---------------------------------------------------------------------------
// tf32 tensor-core projection GEMM body: C = A[M,K] @ B[K,N]
// Block tile 128x128, BK=32, 256 threads (8 warps, each 32x64 warp tile).
// Uses blockIdx.x (col tile) and blockIdx.y (row tile).
// ---------------------------------------------------------------------------
__device__ __forceinline__ void proj_body(const float* __restrict__ A,
                                          const float* __restrict__ B,
                                          float* __restrict__ C) {
    __shared__ __align__(16) unsigned As[128][36];
    __shared__ __align__(16) unsigned Bs[32][136];

    const int t    = threadIdx.x;
    const int lane = t & 31;
    const int warp = t >> 5;
    const int wm   = (warp & 3) * 32;
    const int wn   = (warp >> 2) * 64;
    const int g    = lane >> 2;
    const int tg   = lane & 3;

    const int row0 = blockIdx.y * 128;
    const int col0 = blockIdx.x * 128;

    float c[2][8][4];
#pragma unroll
    for (int mi = 0; mi < 2; mi++)
#pragma unroll
        for (int ni = 0; ni < 8; ni++)
#pragma unroll
            for (int r = 0; r < 4; r++) c[mi][ni][r] = 0.0f;

    for (int k0 = 0; k0 < Dsz; k0 += 32) {
#pragma unroll
        for (int i = 0; i < 4; i++) {
            const int fidx = t + i * 256;
            const int r  = fidx >> 3;
            const int c4 = (fidx & 7) << 2;
            float4 v = *reinterpret_cast<const float4*>(
                A + (long)(row0 + r) * Dsz + k0 + c4);
            uint4 u = {f2tf(v.x), f2tf(v.y), f2tf(v.z), f2tf(v.w)};
            *reinterpret_cast<uint4*>(&As[r][c4]) = u;
        }
#pragma unroll
        for (int i = 0; i < 4; i++) {
            const int fidx = t + i * 256;
            const int r  = fidx >> 5;
            const int c4 = (fidx & 31) << 2;
            float4 v = *reinterpret_cast<const float4*>(
                B + (long)(k0 + r) * Dsz + col0 + c4);
            uint4 u = {f2tf(v.x), f2tf(v.y), f2tf(v.z), f2tf(v.w)};
            *reinterpret_cast<uint4*>(&Bs[r][c4]) = u;
        }
        __syncthreads();

#pragma unroll
        for (int ks = 0; ks < 4; ks++) {
            const int k8 = ks * 8;
            unsigned a[2][4];
#pragma unroll
            for (int mi = 0; mi < 2; mi++) {
                const int mb = wm + mi * 16;
                a[mi][0] = As[mb + g][k8 + tg];
                a[mi][1] = As[mb + g + 8][k8 + tg];
                a[mi][2] = As[mb + g][k8 + tg + 4];
                a[mi][3] = As[mb + g + 8][k8 + tg + 4];
            }
#pragma unroll
            for (int ni = 0; ni < 8; ni++) {
                const int nb = wn + ni * 8;
                unsigned b0 = Bs[k8 + tg][nb + g];
                unsigned b1 = Bs[k8 + tg + 4][nb + g];
#pragma unroll
                for (int mi = 0; mi < 2; mi++)
                    mma_tf32(c[mi][ni], a[mi][0], a[mi][1], a[mi][2], a[mi][3],
                             b0, b1);
            }
        }
        __syncthreads();
    }

#pragma unroll
    for (int mi = 0; mi < 2; mi++) {
#pragma unroll
        for (int ni = 0; ni < 8; ni++) {
            const int row = row0 + wm + mi * 16 + g;
            const int col = col0 + wn + ni * 8 + tg * 2;
            float2 v0 = {c[mi][ni][0], c[mi][ni][1]};
            *reinterpret_cast<float2*>(C + (long)row * Dsz + col) = v0;
            float2 v1 = {c[mi][ni][2], c[mi][ni][3]};
            *reinterpret_cast<float2*>(C + (long)(row + 8) * Dsz + col) = v1;
        }
    }
}

// Batched QKV projection: blockIdx.z selects (input, weight, output).
__global__ void __launch_bounds__(256, 2)
qkv_proj_kernel(const float* __restrict__ q_in, const float* __restrict__ Wq,
                const float* __restrict__ k_in, const float* __restrict__ Wk,
                const float* __restrict__ v_in, const float* __restrict__ Wv,
                float* __restrict__ Qo, float* __restrict__ Ko,
                float* __restrict__ Vo) {
    const int sel = blockIdx.z;
    const float* A = (sel == 0) ? q_in : (sel == 1) ? k_in : v_in;
    const float* B = (sel == 0) ? Wq   : (sel == 1) ? Wk   : Wv;
    float*       C = (sel == 0) ? Qo   : (sel == 1) ? Ko   : Vo;
    proj_body(A, B, C);
}

// Output projection (z=0) + attn normalization (z>=1) in one launch.
// grid (8, 32, 65): z=0 -> proj tile; z in 1..64 -> 256 norm blocks each,
// each norm block scales 4 rows of attn by 1/g_S[row].
__global__ void __launch_bounds__(256, 2)
projnorm_kernel(const float* __restrict__ X, const float* __restrict__ Wo,
                float* __restrict__ out, float* __restrict__ attn) {
    if (blockIdx.z == 0) {
        proj_body(X, Wo, out);
        return;
    }
    const int flat = (blockIdx.z - 1) * 256 + blockIdx.y * 8 + blockIdx.x;
    const int t = threadIdx.x;
#pragma unroll
    for (int i = 0; i < 4; i++) {
        const long r = (long)flat * 4 + i;   // global row in [0, BHsz*Ssz)
        const float ri = 1.0f / g_S[r];
        float* rp = attn + r * Ssz;
#pragma unroll
        for (int j = 0; j < 2; j++) {
            const int idx = (t + j * 256) * 4;
            float4 v = *reinterpret_cast<const float4*>(rp + idx);
            v.x *= ri; v.y *= ri; v.z *= ri; v.w *= ri;
            *reinterpret_cast<float4*>(rp + idx) = v;
        }
    }
}

// ---------------------------------------------------------------------------
// Fused scores + exp + AV kernel (128 q-rows per block).
// Warp-owns-full-rows layout: each warp computes 16 q-rows x all 64 chunk
// cols. The exp'd S fragments are converted in-register (shuffle permute)
// into the A-operand fragments of the AV MMA -> no Es smem buffer, 2 syncs
// per chunk, warp-private row sums.
// Dynamic smem: Qs 128*68 + Ks 64*68 + Vs 64*72 = 70656 B -> 3 CTAs/SM.
// grid (16, 32), 256 threads.
// ---------------------------------------------------------------------------
#define FA_SMEM 70656

__global__ void __launch_bounds__(256, 3)
fused_attn_kernel(const int* __restrict__ mask, float* __restrict__ E) {
    extern __shared__ __align__(16) unsigned sm[];
    unsigned* Qs = sm;                 // [128][68]
    unsigned* Ks = Qs + 128 * 68;      // [64][68]
    unsigned* Vs = Ks + 64 * 68;       // [64][72]

    const int t    = threadIdx.x;
    const int lane = t & 31;
    const int warp = t >> 5;
    const int wm   = warp * 16;        // warp owns rows wm..wm+15
    const int g    = lane >> 2;
    const int tg   = lane & 3;

    const int z = blockIdx.y;
    const int b = z >> 4, h = z & 15;
    const int row0 = blockIdx.x * 128;

    const float* Qg = g_Q + (long)b * Ssz * Dsz + h * DKsz;
    const float* Kg = g_K + (long)b * Ssz * Dsz + h * DKsz;
    const float* Vg = g_V + (long)b * Ssz * Dsz + h * DKsz;
    float* Ez = E + (long)z * Ssz * Ssz;

    // Stage Q tile [128 x 64] as tf32 (once)
#pragma unroll
    for (int i = 0; i < 8; i++) {
        const int fidx = t + i * 256;
        const int r  = fidx >> 4;
        const int c4 = (fidx & 15) << 2;
        float4 v = *reinterpret_cast<const float4*>(
            Qg + (long)(row0 + r) * Dsz + c4);
        uint4 u = {f2tf(v.x), f2tf(v.y), f2tf(v.z), f2tf(v.w)};
        *reinterpret_cast<uint4*>(&Qs[r * 68 + c4]) = u;
    }

    float xacc[8][4];
#pragma unroll
    for (int ni = 0; ni < 8; ni++)
#pragma unroll
        for (int r = 0; r < 4; r++) xacc[ni][r] = 0.0f;
    float rsum0 = 0.0f, rsum1 = 0.0f;   // rows wm+g, wm+g+8

    const float SC = 0.125f * 1.44269504088896f;
    const float CB = -30.0f * 1.44269504088896f;

    const int src1 = (lane & ~3) | (tg >> 1);   // lane holding col tg (pair)
    const int src2 = src1 + 2;                  // lane holding col tg+4

    for (int c = 0; c < Ssz / 64; c++) {
        __syncthreads();   // prior chunk's AV MMA done before Ks/Vs overwrite

        // Stage K chunk [64 n x 64 k] (NT, stride 68) + V chunk [64 k x 64 n]
        // (NN, stride 72) together for deeper MLP.
#pragma unroll
        for (int i = 0; i < 4; i++) {
            const int fidx = t + i * 256;
            const int r  = fidx >> 4;
            const int c4 = (fidx & 15) << 2;
            float4 v = *reinterpret_cast<const float4*>(
                Kg + (long)(c * 64 + r) * Dsz + c4);
            uint4 u = {f2tf(v.x), f2tf(v.y), f2tf(v.z), f2tf(v.w)};
            *reinterpret_cast<uint4*>(&Ks[r * 68 + c4]) = u;
        }
#pragma unroll
        for (int i = 0; i < 4; i++) {
            const int fidx = t + i * 256;
            const int r  = fidx >> 4;
            const int c4 = (fidx & 15) << 2;
            float4 v = *reinterpret_cast<const float4*>(
                Vg + (long)(c * 64 + r) * Dsz + c4);
            uint4 u = {f2tf(v.x), f2tf(v.y), f2tf(v.z), f2tf(v.w)};
            *reinterpret_cast<uint4*>(&Vs[r * 72 + c4]) = u;
        }
        __syncthreads();

        // QK^T MMA: S strip [16 x 64] per warp, K depth 64
        float sacc[8][4];
#pragma unroll
        for (int ni = 0; ni < 8; ni++)
#pragma unroll
            for (int r = 0; r < 4; r++) sacc[ni][r] = 0.0f;

#pragma unroll
        for (int ks = 0; ks < 8; ks++) {
            const int k8 = ks * 8;
            unsigned a0 = Qs[(wm + g) * 68 + k8 + tg];
            unsigned a1 = Qs[(wm + g + 8) * 68 + k8 + tg];
            unsigned a2 = Qs[(wm + g) * 68 + k8 + tg + 4];
            unsigned a3 = Qs[(wm + g + 8) * 68 + k8 + tg + 4];
#pragma unroll
            for (int ni = 0; ni < 8; ni++) {
                const int nb = ni * 8;
                unsigned b0 = Ks[(nb + g) * 68 + k8 + tg];
                unsigned b1 = Ks[(nb + g) * 68 + k8 + tg + 4];
                mma_tf32(sacc[ni], a0, a1, a2, a3, b0, b1);
            }
        }

        // Epilogue: masked exp, write E to gmem, keep tf32 copies in regs.
        unsigned es[8][4];
#pragma unroll
        for (int ni = 0; ni < 8; ni++) {
            const int r0   = wm + g;
            const int col  = ni * 8 + tg * 2;
            const int gcol = c * 64 + col;
            const long mbase = (long)b * Ssz * Ssz + gcol;

            int2 m0 = *reinterpret_cast<const int2*>(
                mask + mbase + (long)(row0 + r0) * Ssz);
            float e00 = (m0.x == 0) ? 0.0f : exp2f(fmaf(sacc[ni][0], SC, CB));
            float e01 = (m0.y == 0) ? 0.0f : exp2f(fmaf(sacc[ni][1], SC, CB));

            int2 m1 = *reinterpret_cast<const int2*>(
                mask + mbase + (long)(row0 + r0 + 8) * Ssz);
            float e10 = (m1.x == 0) ? 0.0f : exp2f(fmaf(sacc[ni][2], SC, CB));
            float e11 = (m1.y == 0) ? 0.0f : exp2f(fmaf(sacc[ni][3], SC, CB));

            float2 v0 = {e00, e01};
            *reinterpret_cast<float2*>(Ez + (long)(row0 + r0) * Ssz + gcol) = v0;
            float2 v1 = {e10, e11};
            *reinterpret_cast<float2*>(Ez + (long)(row0 + r0 + 8) * Ssz + gcol) = v1;

            rsum0 += e00 + e01;
            rsum1 += e10 + e11;

            es[ni][0] = f2tf(e00);
            es[ni][1] = f2tf(e01);
            es[ni][2] = f2tf(e10);
            es[ni][3] = f2tf(e11);
        }

        // AV MMA: X += E_chunk @ V_chunk. A-fragments come from es[] via
        // C-layout -> A-layout lane permutation:
        //   C frag: (g, 2tg), (g, 2tg+1), (g+8, 2tg), (g+8, 2tg+1)
        //   A frag: (g, tg), (g+8, tg), (g, tg+4), (g+8, tg+4)
#pragma unroll
        for (int ki = 0; ki < 8; ki++) {
            unsigned lo1 = __shfl_sync(0xffffffffu, es[ki][0], src1);
            unsigned hi1 = __shfl_sync(0xffffffffu, es[ki][1], src1);
            unsigned lo2 = __shfl_sync(0xffffffffu, es[ki][0], src2);
            unsigned hi2 = __shfl_sync(0xffffffffu, es[ki][1], src2);
            unsigned qo1 = __shfl_sync(0xffffffffu, es[ki][2], src1);
            unsigned qi1 = __shfl_sync(0xffffffffu, es[ki][3], src1);
            unsigned qo2 = __shfl_sync(0xffffffffu, es[ki][2], src2);
            unsigned qi2 = __shfl_sync(0xffffffffu, es[ki][3], src2);
            unsigned a0 = (tg & 1) ? hi1 : lo1;   // (g,    tg)
            unsigned a1 = (tg & 1) ? qi1 : qo1;   // (g+8,  tg)
            unsigned a2 = (tg & 1) ? hi2 : lo2;   // (g,    tg+4)
            unsigned a3 = (tg & 1) ? qi2 : qo2;   // (g+8,  tg+4)

            const int k8 = ki * 8;
#pragma unroll
            for (int ni = 0; ni < 8; ni++) {
                const int nb = ni * 8;
                unsigned b0 = Vs[(k8 + tg) * 72 + nb + g];
                unsigned b1 = Vs[(k8 + tg + 4) * 72 + nb + g];
                mma_tf32(xacc[ni], a0, a1, a2, a3, b0, b1);
            }
        }
    }

    // Warp-private row sums (each warp owns its 16 rows entirely):
    // reduce across the 4 lanes of each row quad.
    rsum0 += __shfl_xor_sync(0xffffffffu, rsum0, 1);
    rsum0 += __shfl_xor_sync(0xffffffffu, rsum0, 2);
    rsum1 += __shfl_xor_sync(0xffffffffu, rsum1, 1);
    rsum1 += __shfl_xor_sync(0xffffffffu, rsum1, 2);
    if (tg == 0) {
        g_S[(long)z * Ssz + row0 + wm + g]     = rsum0;
        g_S[(long)z * Ssz + row0 + wm + g + 8] = rsum1;
    }
    const float ri0 = 1.0f / rsum0;
    const float ri1 = 1.0f / rsum1;

    // X epilogue with row scaling
    float* Xg = g_X + (long)b * Ssz * Dsz + h * DKsz;
#pragma unroll
    for (int ni = 0; ni < 8; ni++) {
        const int col = ni * 8 + tg * 2;
        float2 v0 = {xacc[ni][0] * ri0, xacc[ni][1] * ri0};
        *reinterpret_cast<float2*>(
            Xg + (long)(row0 + wm + g) * Dsz + col) = v0;
        float2 v1 = {xacc[ni][2] * ri1, xacc[ni][3] * ri1};
        *reinterpret_cast<float2*>(
            Xg + (long)(row0 + wm + g + 8) * Dsz + col) = v1;
    }
}

// ---------------------------------------------------------------------------
// Launch
// ---------------------------------------------------------------------------
extern "C" void kernel_launch(void* const* d_in, const int* in_sizes, int n_in,
                              void* d_out, int out_size) {
    const float* query = (const float*)d_in[0];
    const float* key   = (const float*)d_in[1];
    const float* value = (const float*)d_in[2];
    const int*   mask  = (const int*)d_in[3];
    const float* W_q   = (const float*)d_in[4];
    const float* W_k   = (const float*)d_in[5];
    const float* W_v   = (const float*)d_in[6];
    const float* W_o   = (const float*)d_in[7];

    float* out  = (float*)d_out;                        // (B,S,D)
    float* attn = out + (long)Bsz * Ssz * Dsz;          // (B,H,S,S)

    float *Q, *K, *V, *X;
    cudaGetSymbolAddress((void**)&Q, g_Q);
    cudaGetSymbolAddress((void**)&K, g_K);
    cudaGetSymbolAddress((void**)&V, g_V);
    cudaGetSymbolAddress((void**)&X, g_X);

    cudaFuncSetAttribute(fused_attn_kernel,
                         cudaFuncAttributeMaxDynamicSharedMemorySize, FA_SMEM);

    qkv_proj_kernel<<<dim3(Dsz / 128, (Bsz * Ssz) / 128, 3), 256>>>(
        query, W_q, key, W_k, value, W_v, Q, K, V);

    fused_attn_kernel<<<dim3(Ssz / 128, BHsz), 256, FA_SMEM>>>(mask, attn);

    // z=0: out = X @ W_o;  z>=1: attn = E / rowsum (16384 norm blocks)
    projnorm_kernel<<<dim3(Dsz / 128, (Bsz * Ssz) / 128, 65), 256>>>(
        X, W_o, out, attn);
}